// round 12
// baseline (speedup 1.0000x reference)
#include <cuda_runtime.h>
#include <cuda_bf16.h>
#include <cuda_fp16.h>
#include <mma.h>
#include <cstdint>

using namespace nvcuda;

#define NODES_MAX 100000
#define EDGES_MAX 300000
#define HDIM 256
#define FIN 128

// ---------------- scratch (allocation-free rule: __device__ globals) ----------------
__device__ float g_dinv[NODES_MAX];
__device__ int   g_deg[NODES_MAX];
__device__ int   g_off[NODES_MAX + 1];
__device__ int   g_cur[NODES_MAX];
__device__ int   g_esrc[EDGES_MAX];
__device__ int   g_bsum[512];
__device__ int   g_bpre[512];
// split-bf16 weights [K,256], 5 slots
__device__ __align__(16) __nv_bfloat16 g_wh[5 * 256 * 256];
__device__ __align__(16) __nv_bfloat16 g_wl[5 * 256 * 256];
// split-bf16 activations
__device__ __align__(16) __nv_bfloat16 g_xh[(size_t)NODES_MAX * FIN];
__device__ __align__(16) __nv_bfloat16 g_xl[(size_t)NODES_MAX * FIN];
__device__ __align__(16) __nv_bfloat16 g_th[(size_t)NODES_MAX * HDIM];
__device__ __align__(16) __nv_bfloat16 g_tl[(size_t)NODES_MAX * HDIM];
__device__ __align__(16) __nv_bfloat16 g_hh[(size_t)NODES_MAX * HDIM];
__device__ __align__(16) __nv_bfloat16 g_hl[(size_t)NODES_MAX * HDIM];
// fp16 message matrix
__device__ __align__(16) __half g_mf[(size_t)NODES_MAX * HDIM];

// ---------------- degree / norm / CSR build ----------------
__global__ void init_deg_kernel(int* deg, int n) {
    int i = blockIdx.x * blockDim.x + threadIdx.x;
    if (i < n) deg[i] = 1;
}
__global__ void count_deg_kernel(const int* __restrict__ dst, int* deg, int E) {
    int i = blockIdx.x * blockDim.x + threadIdx.x;
    if (i < E) atomicAdd(&deg[dst[i]], 1);
}
__global__ void dinv_kernel(const int* __restrict__ deg, float* dinv, int n) {
    int i = blockIdx.x * blockDim.x + threadIdx.x;
    if (i < n) dinv[i] = rsqrtf((float)deg[i]);
}
__global__ void bsum_kernel(const int* __restrict__ deg, int* bsum, int n) {
    __shared__ int sh[256];
    int i = blockIdx.x * 256 + threadIdx.x;
    sh[threadIdx.x] = (i < n) ? deg[i] - 1 : 0;
    __syncthreads();
    for (int o = 128; o > 0; o >>= 1) {
        if (threadIdx.x < o) sh[threadIdx.x] += sh[threadIdx.x + o];
        __syncthreads();
    }
    if (threadIdx.x == 0) bsum[blockIdx.x] = sh[0];
}
__global__ void bscan_kernel(const int* __restrict__ bsum, int* bpre, int nb, int* off, int n) {
    __shared__ int sh[512];
    int t = threadIdx.x;
    int v = (t < nb) ? bsum[t] : 0;
    sh[t] = v; __syncthreads();
    for (int o = 1; o < 512; o <<= 1) {
        int u = (t >= o) ? sh[t - o] : 0;
        __syncthreads();
        sh[t] += u;
        __syncthreads();
    }
    if (t < nb) bpre[t] = sh[t] - v;
    if (t == 511) off[n] = sh[511];
}
__global__ void off_kernel(const int* __restrict__ deg, const int* __restrict__ bpre,
                           int* __restrict__ off, int* __restrict__ cur, int n) {
    __shared__ int sh[256];
    int i = blockIdx.x * 256 + threadIdx.x;
    int v = (i < n) ? deg[i] - 1 : 0;
    sh[threadIdx.x] = v; __syncthreads();
    for (int o = 1; o < 256; o <<= 1) {
        int u = (threadIdx.x >= o) ? sh[threadIdx.x - o] : 0;
        __syncthreads();
        sh[threadIdx.x] += u;
        __syncthreads();
    }
    if (i < n) {
        int val = bpre[blockIdx.x] + sh[threadIdx.x] - v;
        off[i] = val;
        cur[i] = val;
    }
}
__global__ void fill_kernel(const int* __restrict__ src, const int* __restrict__ dst,
                            int* cur, int* __restrict__ esrc, int E) {
    int i = blockIdx.x * blockDim.x + threadIdx.x;
    if (i < E) {
        int d = dst[i];
        int p = atomicAdd(&cur[d], 1);
        esrc[p] = src[i];
    }
}

// ---------------- fp32 -> split hi/lo bf16 (elementwise, layout preserved) ----------------
__global__ void wprep_kernel(const float* __restrict__ W, __nv_bfloat16* __restrict__ Wh,
                             __nv_bfloat16* __restrict__ Wl, int total) {
    int idx = blockIdx.x * 256 + threadIdx.x;
    if (idx >= total) return;
    float f = W[idx];
    __nv_bfloat16 hb = __float2bfloat16_rn(f);
    Wh[idx] = hb;
    Wl[idx] = __float2bfloat16_rn(f - __bfloat162float(hb));
}
// combined w2 + gcn weights (contiguous slots 1..1+L)
__global__ void wprep2_kernel(const float* __restrict__ w2, const float* __restrict__ gw,
                              __nv_bfloat16* __restrict__ Wh, __nv_bfloat16* __restrict__ Wl,
                              int per, int total) {
    int idx = blockIdx.x * 256 + threadIdx.x;
    if (idx >= total) return;
    float f = (idx < per) ? w2[idx] : gw[idx - per];
    __nv_bfloat16 hb = __float2bfloat16_rn(f);
    Wh[idx] = hb;
    Wl[idx] = __float2bfloat16_rn(f - __bfloat162float(hb));
}

// ---------------- all-async double-buffered split-bf16 wmma GEMM ----------------
// C[M,256] = A@W. A = (Ah,Al) [M,K] bf16 row-major, B = (Bh,Bl) [K,256].
// Output: Cf (fp16) if non-null, else split (Ch, Cl) bf16.
#define PADA 40
#define PADB 136
#define A_ELE (128 * PADA)                 // 5120 elems
#define B_ELE (32 * PADB)                  // 4352 elems
#define STAGE_ELE (2 * A_ELE + 2 * B_ELE)  // 18944 elems = 37888 B
#define WSMEM (2 * STAGE_ELE * 2)          // 75776 B (fp32 epilogue stage 65536 fits)

__device__ __forceinline__ void cp16p(void* sdst, const void* g, int srcsz) {
    uint32_t sa = (uint32_t)__cvta_generic_to_shared(sdst);
    asm volatile("cp.async.cg.shared.global [%0], [%1], 16, %2;"
                 :: "r"(sa), "l"(g), "r"(srcsz));
}

__global__ __launch_bounds__(256)
void wgemm_kernel(const __nv_bfloat16* __restrict__ Ah, const __nv_bfloat16* __restrict__ Al,
                  const __nv_bfloat16* __restrict__ Bh, const __nv_bfloat16* __restrict__ Bl,
                  const float* __restrict__ bias,
                  __half* __restrict__ Cf, __nv_bfloat16* __restrict__ Ch,
                  __nv_bfloat16* __restrict__ Cl,
                  int M, int K, int relu)
{
    extern __shared__ char smem[];
    __nv_bfloat16* sbase = (__nv_bfloat16*)smem;
    float* stage = (float*)smem;
    int tid = threadIdx.x;
    int wid = tid >> 5, wm = wid >> 2, wn = wid & 3;
    int row0 = blockIdx.x * 128, col0 = blockIdx.y * 128;

    wmma::fragment<wmma::accumulator, 16, 16, 16, float> acc[4][2];
    #pragma unroll
    for (int i = 0; i < 4; i++)
        #pragma unroll
        for (int j = 0; j < 2; j++) wmma::fill_fragment(acc[i][j], 0.0f);

    int NC = K >> 5;

    #define ISSUE(kc, s) do { \
        __nv_bfloat16* st = sbase + (s) * STAGE_ELE; \
        _Pragma("unroll") \
        for (int it = 0; it < 2; it++) { \
            int idx = it * 256 + tid; \
            int ar = idx >> 2, aseg = (idx & 3) * 8; \
            int grow = row0 + ar; \
            int ps = (grow < M) ? 16 : 0; \
            size_t ga = (size_t)(ps ? grow : 0) * K + (kc) * 32 + aseg; \
            cp16p(st + ar * PADA + aseg, Ah + ga, ps); \
            cp16p(st + A_ELE + ar * PADA + aseg, Al + ga, ps); \
            int br = idx >> 4, bseg = (idx & 15) * 8; \
            size_t gb = (size_t)((kc) * 32 + br) * 256 + col0 + bseg; \
            cp16p(st + 2 * A_ELE + br * PADB + bseg, Bh + gb, 16); \
            cp16p(st + 2 * A_ELE + B_ELE + br * PADB + bseg, Bl + gb, 16); \
        } \
        asm volatile("cp.async.commit_group;"); } while (0)

    ISSUE(0, 0);

    for (int kc = 0; kc < NC; kc++) {
        int s = kc & 1;
        if (kc + 1 < NC) {
            ISSUE(kc + 1, s ^ 1);
            asm volatile("cp.async.wait_group 1;" ::: "memory");
        } else {
            asm volatile("cp.async.wait_group 0;" ::: "memory");
        }
        __syncthreads();

        __nv_bfloat16* sAh = sbase + s * STAGE_ELE;
        __nv_bfloat16* sAl = sAh + A_ELE;
        __nv_bfloat16* sBh = sAh + 2 * A_ELE;
        __nv_bfloat16* sBl = sBh + B_ELE;

        #pragma unroll
        for (int ks = 0; ks < 2; ks++) {
            wmma::fragment<wmma::matrix_b, 16, 16, 16, __nv_bfloat16, wmma::row_major> bh[2], bl[2];
            #pragma unroll
            for (int j = 0; j < 2; j++) {
                wmma::load_matrix_sync(bh[j], sBh + (ks * 16) * PADB + wn * 32 + j * 16, PADB);
                wmma::load_matrix_sync(bl[j], sBl + (ks * 16) * PADB + wn * 32 + j * 16, PADB);
            }
            #pragma unroll
            for (int i = 0; i < 4; i++) {
                wmma::fragment<wmma::matrix_a, 16, 16, 16, __nv_bfloat16, wmma::row_major> ah, al;
                wmma::load_matrix_sync(ah, sAh + (wm * 64 + i * 16) * PADA + ks * 16, PADA);
                wmma::load_matrix_sync(al, sAl + (wm * 64 + i * 16) * PADA + ks * 16, PADA);
                #pragma unroll
                for (int j = 0; j < 2; j++) {
                    wmma::mma_sync(acc[i][j], ah, bh[j], acc[i][j]);
                    wmma::mma_sync(acc[i][j], ah, bl[j], acc[i][j]);
                    wmma::mma_sync(acc[i][j], al, bh[j], acc[i][j]);
                }
            }
        }
        __syncthreads();
    }
    #undef ISSUE

    #pragma unroll
    for (int i = 0; i < 4; i++)
        #pragma unroll
        for (int j = 0; j < 2; j++)
            wmma::store_matrix_sync(stage + (wm * 64 + i * 16) * 128 + wn * 32 + j * 16,
                                    acc[i][j], 128, wmma::mem_row_major);
    __syncthreads();

    #pragma unroll
    for (int it = 0; it < 16; it++) {
        int idx = it * 256 + tid;
        int r = idx >> 5;
        int c4 = (idx & 31) * 4;
        int grow = row0 + r;
        if (grow < M) {
            float4 v = *(float4*)(stage + r * 128 + c4);
            if (bias) {
                v.x += bias[col0 + c4 + 0]; v.y += bias[col0 + c4 + 1];
                v.z += bias[col0 + c4 + 2]; v.w += bias[col0 + c4 + 3];
            }
            if (relu) {
                v.x = fmaxf(v.x, 0.f); v.y = fmaxf(v.y, 0.f);
                v.z = fmaxf(v.z, 0.f); v.w = fmaxf(v.w, 0.f);
            }
            size_t o = (size_t)grow * 256 + col0 + c4;
            if (Cf) {
                __half2 ha = __floats2half2_rn(v.x, v.y);
                __half2 hb = __floats2half2_rn(v.z, v.w);
                uint2 pk;
                pk.x = *(uint32_t*)&ha; pk.y = *(uint32_t*)&hb;
                *(uint2*)(Cf + o) = pk;
            } else {
                uint32_t h01, h23, l01, l23;
                asm("cvt.rn.bf16x2.f32 %0, %1, %2;" : "=r"(h01) : "f"(v.y), "f"(v.x));
                asm("cvt.rn.bf16x2.f32 %0, %1, %2;" : "=r"(h23) : "f"(v.w), "f"(v.z));
                float r0 = v.x - __uint_as_float(h01 << 16);
                float r1 = v.y - __uint_as_float(h01 & 0xFFFF0000u);
                float r2 = v.z - __uint_as_float(h23 << 16);
                float r3 = v.w - __uint_as_float(h23 & 0xFFFF0000u);
                asm("cvt.rn.bf16x2.f32 %0, %1, %2;" : "=r"(l01) : "f"(r1), "f"(r0));
                asm("cvt.rn.bf16x2.f32 %0, %1, %2;" : "=r"(l23) : "f"(r3), "f"(r2));
                *(uint2*)(Ch + o) = make_uint2(h01, h23);
                *(uint2*)(Cl + o) = make_uint2(l01, l23);
            }
        }
    }
}

// ---------------- fused aggregate: 2 warps per node, fp16 gather ----------------
// out = relu(bias + dinv[i]^2*m[i] + sum dinv[s]*dinv[i]*m[s]); fp32 out OR split-bf16 out.
__global__ __launch_bounds__(256)
void aggregate_kernel(const __half* __restrict__ m, const int* __restrict__ off,
                      const int* __restrict__ esrc, const float* __restrict__ dinv,
                      const float* __restrict__ bias, float* __restrict__ outf,
                      __nv_bfloat16* __restrict__ outh, __nv_bfloat16* __restrict__ outl, int n)
{
    int gw = (blockIdx.x * blockDim.x + threadIdx.x) >> 5;
    int node = gw >> 1;
    int half_ = gw & 1;
    int lane = threadIdx.x & 31;
    if (node >= n) return;
    int j = half_ * 32 + lane;   // 4-col group index 0..63

    float di = __ldg(&dinv[node]);
    float4 a = ((const float4*)bias)[j];

    float ws = di * di;
    {
        uint2 u = ((const uint2*)(m + (size_t)node * HDIM))[j];
        float2 f0 = __half22float2(*(__half2*)&u.x);
        float2 f1 = __half22float2(*(__half2*)&u.y);
        a.x = fmaf(ws, f0.x, a.x); a.y = fmaf(ws, f0.y, a.y);
        a.z = fmaf(ws, f1.x, a.z); a.w = fmaf(ws, f1.y, a.w);
    }

    int e = __ldg(&off[node]);
    int e1 = __ldg(&off[node + 1]);

    if (e < e1) {
        int s = __ldg(&esrc[e]);
        float wd = __ldg(&dinv[s]);
        while (true) {
            uint2 u = ((const uint2*)(m + (size_t)s * HDIM))[j];
            int sn = 0; float wdn = 0.f;
            if (e + 1 < e1) { sn = __ldg(&esrc[e + 1]); wdn = __ldg(&dinv[sn]); }
            float w = wd * di;
            float2 f0 = __half22float2(*(__half2*)&u.x);
            float2 f1 = __half22float2(*(__half2*)&u.y);
            a.x = fmaf(w, f0.x, a.x); a.y = fmaf(w, f0.y, a.y);
            a.z = fmaf(w, f1.x, a.z); a.w = fmaf(w, f1.y, a.w);
            e++;
            if (e >= e1) break;
            s = sn; wd = wdn;
        }
    }

    a.x = fmaxf(a.x, 0.f); a.y = fmaxf(a.y, 0.f);
    a.z = fmaxf(a.z, 0.f); a.w = fmaxf(a.w, 0.f);

    if (outf) {
        ((float4*)(outf + (size_t)node * HDIM))[j] = a;
    } else {
        uint32_t h01, h23, l01, l23;
        asm("cvt.rn.bf16x2.f32 %0, %1, %2;" : "=r"(h01) : "f"(a.y), "f"(a.x));
        asm("cvt.rn.bf16x2.f32 %0, %1, %2;" : "=r"(h23) : "f"(a.w), "f"(a.z));
        float r0 = a.x - __uint_as_float(h01 << 16);
        float r1 = a.y - __uint_as_float(h01 & 0xFFFF0000u);
        float r2 = a.z - __uint_as_float(h23 << 16);
        float r3 = a.w - __uint_as_float(h23 & 0xFFFF0000u);
        asm("cvt.rn.bf16x2.f32 %0, %1, %2;" : "=r"(l01) : "f"(r1), "f"(r0));
        asm("cvt.rn.bf16x2.f32 %0, %1, %2;" : "=r"(l23) : "f"(r3), "f"(r2));
        ((uint2*)(outh + (size_t)node * HDIM))[j] = make_uint2(h01, h23);
        ((uint2*)(outl + (size_t)node * HDIM))[j] = make_uint2(l01, l23);
    }
}

extern "C" void kernel_launch(void* const* d_in, const int* in_sizes, int n_in,
                              void* d_out, int out_size)
{
    const float* x  = (const float*)d_in[0];
    const int*   ei = (const int*)d_in[1];
    const float* w1 = (const float*)d_in[2];
    const float* b1 = (const float*)d_in[3];
    const float* w2 = (const float*)d_in[4];
    const float* b2 = (const float*)d_in[5];
    const float* gw = (const float*)d_in[6];
    const float* gb = (const float*)d_in[7];

    int N = in_sizes[0] / FIN;
    int E = in_sizes[1] / 2;
    int L = in_sizes[6] / (HDIM * HDIM);
    const int* srcp = ei;
    const int* dstp = ei + E;

    float *dinv;
    int *deg, *off, *cur, *esrc, *bsum, *bpre;
    __nv_bfloat16 *wh, *wl, *xh, *xl, *th, *tl, *hh, *hl;
    __half *mf;
    cudaGetSymbolAddress((void**)&dinv, g_dinv);
    cudaGetSymbolAddress((void**)&deg,  g_deg);
    cudaGetSymbolAddress((void**)&off,  g_off);
    cudaGetSymbolAddress((void**)&cur,  g_cur);
    cudaGetSymbolAddress((void**)&esrc, g_esrc);
    cudaGetSymbolAddress((void**)&bsum, g_bsum);
    cudaGetSymbolAddress((void**)&bpre, g_bpre);
    cudaGetSymbolAddress((void**)&wh,   g_wh);
    cudaGetSymbolAddress((void**)&wl,   g_wl);
    cudaGetSymbolAddress((void**)&xh,   g_xh);
    cudaGetSymbolAddress((void**)&xl,   g_xl);
    cudaGetSymbolAddress((void**)&th,   g_th);
    cudaGetSymbolAddress((void**)&tl,   g_tl);
    cudaGetSymbolAddress((void**)&hh,   g_hh);
    cudaGetSymbolAddress((void**)&hl,   g_hl);
    cudaGetSymbolAddress((void**)&mf,   g_mf);

    cudaFuncSetAttribute(wgemm_kernel, cudaFuncAttributeMaxDynamicSharedMemorySize, WSMEM);

    int nb = (N + 255) / 256;
    int eb = (E + 255) / 256;
    const size_t WS = 256 * 256;
    dim3 gemm_grid((N + 127) / 128, 2);

    // (1-3) prep passes
    wprep_kernel<<<(N * FIN + 255) / 256, 256>>>(x, xh, xl, N * FIN);
    wprep_kernel<<<(FIN * 256 + 255) / 256, 256>>>(w1, wh, wl, FIN * 256);
    wprep2_kernel<<<((1 + L) * (int)WS + 255) / 256, 256>>>(w2, gw, wh + WS, wl + WS,
                                                            (int)WS, (1 + L) * (int)WS);

    // (4) enc1 — profiled slot
    wgemm_kernel<<<gemm_grid, 256, WSMEM>>>(xh, xl, wh, wl, b1,
                                            nullptr, th, tl, N, FIN, 1);
    // (5) enc2
    wgemm_kernel<<<gemm_grid, 256, WSMEM>>>(th, tl, wh + WS, wl + WS, b2,
                                            nullptr, hh, hl, N, HDIM, 0);

    // (6-12) degree/CSR build
    init_deg_kernel<<<nb, 256>>>(deg, N);
    count_deg_kernel<<<eb, 256>>>(dstp, deg, E);
    dinv_kernel<<<nb, 256>>>(deg, dinv, N);
    bsum_kernel<<<nb, 256>>>(deg, bsum, N);
    bscan_kernel<<<1, 512>>>(bsum, bpre, nb, off, N);
    off_kernel<<<nb, 256>>>(deg, bpre, off, cur, N);
    fill_kernel<<<eb, 256>>>(srcp, dstp, cur, esrc, E);

    int agg_blocks = (int)(((long long)N * 64 + 255) / 256);

    for (int l = 0; l < L; l++) {
        wgemm_kernel<<<gemm_grid, 256, WSMEM>>>(hh, hl, wh + WS * (2 + l), wl + WS * (2 + l),
                                                nullptr, mf, nullptr, nullptr, N, HDIM, 0);
        if (l == L - 1)
            aggregate_kernel<<<agg_blocks, 256>>>(mf, off, esrc, dinv, gb + (size_t)l * HDIM,
                                                  (float*)d_out, nullptr, nullptr, N);
        else
            aggregate_kernel<<<agg_blocks, 256>>>(mf, off, esrc, dinv, gb + (size_t)l * HDIM,
                                                  nullptr, hh, hl, N);
    }
}

// round 13
// speedup vs baseline: 1.1659x; 1.1659x over previous
#include <cuda_runtime.h>
#include <cuda_bf16.h>
#include <cuda_fp16.h>
#include <mma.h>
#include <cstdint>

using namespace nvcuda;

#define NODES_MAX 100000
#define EDGES_MAX 300000
#define HDIM 256
#define FIN 128

// ---------------- scratch (allocation-free rule: __device__ globals) ----------------
__device__ float g_dinv[NODES_MAX];
__device__ int   g_deg[NODES_MAX];
__device__ int   g_off[NODES_MAX + 1];
__device__ int   g_cur[NODES_MAX];
__device__ int   g_esrc[EDGES_MAX];
__device__ int   g_bsum[512];
__device__ int   g_bpre[512];
// split-bf16 weights [K,256], 5 slots
__device__ __align__(16) __nv_bfloat16 g_wh[5 * 256 * 256];
__device__ __align__(16) __nv_bfloat16 g_wl[5 * 256 * 256];
// split-bf16 activations
__device__ __align__(16) __nv_bfloat16 g_xh[(size_t)NODES_MAX * FIN];
__device__ __align__(16) __nv_bfloat16 g_xl[(size_t)NODES_MAX * FIN];
__device__ __align__(16) __nv_bfloat16 g_th[(size_t)NODES_MAX * HDIM];
__device__ __align__(16) __nv_bfloat16 g_tl[(size_t)NODES_MAX * HDIM];
__device__ __align__(16) __nv_bfloat16 g_hh[(size_t)NODES_MAX * HDIM];
__device__ __align__(16) __nv_bfloat16 g_hl[(size_t)NODES_MAX * HDIM];
// fp16 message matrix
__device__ __align__(16) __half g_mf[(size_t)NODES_MAX * HDIM];

// ---------------- degree / norm / CSR build ----------------
__global__ void init_deg_kernel(int* deg, int n) {
    int i = blockIdx.x * blockDim.x + threadIdx.x;
    if (i < n) deg[i] = 1;
}
__global__ void count_deg_kernel(const int* __restrict__ dst, int* deg, int E) {
    int i = blockIdx.x * blockDim.x + threadIdx.x;
    if (i < E) atomicAdd(&deg[dst[i]], 1);
}
__global__ void dinv_kernel(const int* __restrict__ deg, float* dinv, int n) {
    int i = blockIdx.x * blockDim.x + threadIdx.x;
    if (i < n) dinv[i] = rsqrtf((float)deg[i]);
}
__global__ void bsum_kernel(const int* __restrict__ deg, int* bsum, int n) {
    __shared__ int sh[256];
    int i = blockIdx.x * 256 + threadIdx.x;
    sh[threadIdx.x] = (i < n) ? deg[i] - 1 : 0;
    __syncthreads();
    for (int o = 128; o > 0; o >>= 1) {
        if (threadIdx.x < o) sh[threadIdx.x] += sh[threadIdx.x + o];
        __syncthreads();
    }
    if (threadIdx.x == 0) bsum[blockIdx.x] = sh[0];
}
__global__ void bscan_kernel(const int* __restrict__ bsum, int* bpre, int nb, int* off, int n) {
    __shared__ int sh[512];
    int t = threadIdx.x;
    int v = (t < nb) ? bsum[t] : 0;
    sh[t] = v; __syncthreads();
    for (int o = 1; o < 512; o <<= 1) {
        int u = (t >= o) ? sh[t - o] : 0;
        __syncthreads();
        sh[t] += u;
        __syncthreads();
    }
    if (t < nb) bpre[t] = sh[t] - v;
    if (t == 511) off[n] = sh[511];
}
__global__ void off_kernel(const int* __restrict__ deg, const int* __restrict__ bpre,
                           int* __restrict__ off, int* __restrict__ cur, int n) {
    __shared__ int sh[256];
    int i = blockIdx.x * 256 + threadIdx.x;
    int v = (i < n) ? deg[i] - 1 : 0;
    sh[threadIdx.x] = v; __syncthreads();
    for (int o = 1; o < 256; o <<= 1) {
        int u = (threadIdx.x >= o) ? sh[threadIdx.x - o] : 0;
        __syncthreads();
        sh[threadIdx.x] += u;
        __syncthreads();
    }
    if (i < n) {
        int val = bpre[blockIdx.x] + sh[threadIdx.x] - v;
        off[i] = val;
        cur[i] = val;
    }
}
__global__ void fill_kernel(const int* __restrict__ src, const int* __restrict__ dst,
                            int* cur, int* __restrict__ esrc, int E) {
    int i = blockIdx.x * blockDim.x + threadIdx.x;
    if (i < E) {
        int d = dst[i];
        int p = atomicAdd(&cur[d], 1);
        esrc[p] = src[i];
    }
}

// ---------------- fp32 -> split hi/lo bf16 ----------------
__global__ void wprep_kernel(const float* __restrict__ W, __nv_bfloat16* __restrict__ Wh,
                             __nv_bfloat16* __restrict__ Wl, int total) {
    int idx = blockIdx.x * 256 + threadIdx.x;
    if (idx >= total) return;
    float f = W[idx];
    __nv_bfloat16 hb = __float2bfloat16_rn(f);
    Wh[idx] = hb;
    Wl[idx] = __float2bfloat16_rn(f - __bfloat162float(hb));
}
__global__ void wprep2_kernel(const float* __restrict__ w2, const float* __restrict__ gw,
                              __nv_bfloat16* __restrict__ Wh, __nv_bfloat16* __restrict__ Wl,
                              int per, int total) {
    int idx = blockIdx.x * 256 + threadIdx.x;
    if (idx >= total) return;
    float f = (idx < per) ? w2[idx] : gw[idx - per];
    __nv_bfloat16 hb = __float2bfloat16_rn(f);
    Wh[idx] = hb;
    Wl[idx] = __float2bfloat16_rn(f - __bfloat162float(hb));
}

// ---------------- all-async double-buffered split-bf16 wmma GEMM ----------------
#define PADA 40
#define PADB 136
#define A_ELE (128 * PADA)
#define B_ELE (32 * PADB)
#define STAGE_ELE (2 * A_ELE + 2 * B_ELE)
#define WSMEM (2 * STAGE_ELE * 2)          // 75776 B; 2 CTAs = 151552 < 228KB

__device__ __forceinline__ void cp16p(void* sdst, const void* g, int srcsz) {
    uint32_t sa = (uint32_t)__cvta_generic_to_shared(sdst);
    asm volatile("cp.async.cg.shared.global [%0], [%1], 16, %2;"
                 :: "r"(sa), "l"(g), "r"(srcsz));
}

__global__ __launch_bounds__(256, 2)   // cap 128 regs -> 2 CTAs/SM
void wgemm_kernel(const __nv_bfloat16* __restrict__ Ah, const __nv_bfloat16* __restrict__ Al,
                  const __nv_bfloat16* __restrict__ Bh, const __nv_bfloat16* __restrict__ Bl,
                  const float* __restrict__ bias,
                  __half* __restrict__ Cf, __nv_bfloat16* __restrict__ Ch,
                  __nv_bfloat16* __restrict__ Cl,
                  int M, int K, int relu)
{
    extern __shared__ char smem[];
    __nv_bfloat16* sbase = (__nv_bfloat16*)smem;
    float* stage = (float*)smem;
    int tid = threadIdx.x;
    int wid = tid >> 5, wm = wid >> 2, wn = wid & 3;
    int row0 = blockIdx.x * 128, col0 = blockIdx.y * 128;

    wmma::fragment<wmma::accumulator, 16, 16, 16, float> acc[4][2];
    #pragma unroll
    for (int i = 0; i < 4; i++)
        #pragma unroll
        for (int j = 0; j < 2; j++) wmma::fill_fragment(acc[i][j], 0.0f);

    int NC = K >> 5;

    #define ISSUE(kc, s) do { \
        __nv_bfloat16* st = sbase + (s) * STAGE_ELE; \
        _Pragma("unroll") \
        for (int it = 0; it < 2; it++) { \
            int idx = it * 256 + tid; \
            int ar = idx >> 2, aseg = (idx & 3) * 8; \
            int grow = row0 + ar; \
            int ps = (grow < M) ? 16 : 0; \
            size_t ga = (size_t)(ps ? grow : 0) * K + (kc) * 32 + aseg; \
            cp16p(st + ar * PADA + aseg, Ah + ga, ps); \
            cp16p(st + A_ELE + ar * PADA + aseg, Al + ga, ps); \
            int br = idx >> 4, bseg = (idx & 15) * 8; \
            size_t gb = (size_t)((kc) * 32 + br) * 256 + col0 + bseg; \
            cp16p(st + 2 * A_ELE + br * PADB + bseg, Bh + gb, 16); \
            cp16p(st + 2 * A_ELE + B_ELE + br * PADB + bseg, Bl + gb, 16); \
        } \
        asm volatile("cp.async.commit_group;"); } while (0)

    ISSUE(0, 0);

    for (int kc = 0; kc < NC; kc++) {
        int s = kc & 1;
        if (kc + 1 < NC) {
            ISSUE(kc + 1, s ^ 1);
            asm volatile("cp.async.wait_group 1;" ::: "memory");
        } else {
            asm volatile("cp.async.wait_group 0;" ::: "memory");
        }
        __syncthreads();

        __nv_bfloat16* sAh = sbase + s * STAGE_ELE;
        __nv_bfloat16* sAl = sAh + A_ELE;
        __nv_bfloat16* sBh = sAh + 2 * A_ELE;
        __nv_bfloat16* sBl = sBh + B_ELE;

        #pragma unroll
        for (int ks = 0; ks < 2; ks++) {
            wmma::fragment<wmma::matrix_b, 16, 16, 16, __nv_bfloat16, wmma::row_major> bh[2], bl[2];
            #pragma unroll
            for (int j = 0; j < 2; j++) {
                wmma::load_matrix_sync(bh[j], sBh + (ks * 16) * PADB + wn * 32 + j * 16, PADB);
                wmma::load_matrix_sync(bl[j], sBl + (ks * 16) * PADB + wn * 32 + j * 16, PADB);
            }
            #pragma unroll
            for (int i = 0; i < 4; i++) {
                wmma::fragment<wmma::matrix_a, 16, 16, 16, __nv_bfloat16, wmma::row_major> ah, al;
                wmma::load_matrix_sync(ah, sAh + (wm * 64 + i * 16) * PADA + ks * 16, PADA);
                wmma::load_matrix_sync(al, sAl + (wm * 64 + i * 16) * PADA + ks * 16, PADA);
                #pragma unroll
                for (int j = 0; j < 2; j++) {
                    wmma::mma_sync(acc[i][j], ah, bh[j], acc[i][j]);
                    wmma::mma_sync(acc[i][j], ah, bl[j], acc[i][j]);
                    wmma::mma_sync(acc[i][j], al, bh[j], acc[i][j]);
                }
            }
        }
        __syncthreads();
    }
    #undef ISSUE

    #pragma unroll
    for (int i = 0; i < 4; i++)
        #pragma unroll
        for (int j = 0; j < 2; j++)
            wmma::store_matrix_sync(stage + (wm * 64 + i * 16) * 128 + wn * 32 + j * 16,
                                    acc[i][j], 128, wmma::mem_row_major);
    __syncthreads();

    #pragma unroll
    for (int it = 0; it < 16; it++) {
        int idx = it * 256 + tid;
        int r = idx >> 5;
        int c4 = (idx & 31) * 4;
        int grow = row0 + r;
        if (grow < M) {
            float4 v = *(float4*)(stage + r * 128 + c4);
            if (bias) {
                v.x += __ldg(bias + col0 + c4 + 0); v.y += __ldg(bias + col0 + c4 + 1);
                v.z += __ldg(bias + col0 + c4 + 2); v.w += __ldg(bias + col0 + c4 + 3);
            }
            if (relu) {
                v.x = fmaxf(v.x, 0.f); v.y = fmaxf(v.y, 0.f);
                v.z = fmaxf(v.z, 0.f); v.w = fmaxf(v.w, 0.f);
            }
            size_t o = (size_t)grow * 256 + col0 + c4;
            if (Cf) {
                __half2 ha = __floats2half2_rn(v.x, v.y);
                __half2 hb = __floats2half2_rn(v.z, v.w);
                uint2 pk;
                pk.x = *(uint32_t*)&ha; pk.y = *(uint32_t*)&hb;
                *(uint2*)(Cf + o) = pk;
            } else {
                uint32_t h01, h23, l01, l23;
                asm("cvt.rn.bf16x2.f32 %0, %1, %2;" : "=r"(h01) : "f"(v.y), "f"(v.x));
                asm("cvt.rn.bf16x2.f32 %0, %1, %2;" : "=r"(h23) : "f"(v.w), "f"(v.z));
                float r0 = v.x - __uint_as_float(h01 << 16);
                float r1 = v.y - __uint_as_float(h01 & 0xFFFF0000u);
                float r2 = v.z - __uint_as_float(h23 << 16);
                float r3 = v.w - __uint_as_float(h23 & 0xFFFF0000u);
                asm("cvt.rn.bf16x2.f32 %0, %1, %2;" : "=r"(l01) : "f"(r1), "f"(r0));
                asm("cvt.rn.bf16x2.f32 %0, %1, %2;" : "=r"(l23) : "f"(r3), "f"(r2));
                *(uint2*)(Ch + o) = make_uint2(h01, h23);
                *(uint2*)(Cl + o) = make_uint2(l01, l23);
            }
        }
    }
}

// ---------------- fused aggregate: 2 warps per node, fp16 gather ----------------
__global__ __launch_bounds__(256)
void aggregate_kernel(const __half* __restrict__ m, const int* __restrict__ off,
                      const int* __restrict__ esrc, const float* __restrict__ dinv,
                      const float* __restrict__ bias, float* __restrict__ outf,
                      __nv_bfloat16* __restrict__ outh, __nv_bfloat16* __restrict__ outl, int n)
{
    int gw = (blockIdx.x * blockDim.x + threadIdx.x) >> 5;
    int node = gw >> 1;
    int half_ = gw & 1;
    int lane = threadIdx.x & 31;
    if (node >= n) return;
    int j = half_ * 32 + lane;

    float di = __ldg(&dinv[node]);
    float4 a = ((const float4*)bias)[j];

    float ws = di * di;
    {
        uint2 u = ((const uint2*)(m + (size_t)node * HDIM))[j];
        float2 f0 = __half22float2(*(__half2*)&u.x);
        float2 f1 = __half22float2(*(__half2*)&u.y);
        a.x = fmaf(ws, f0.x, a.x); a.y = fmaf(ws, f0.y, a.y);
        a.z = fmaf(ws, f1.x, a.z); a.w = fmaf(ws, f1.y, a.w);
    }

    int e = __ldg(&off[node]);
    int e1 = __ldg(&off[node + 1]);

    if (e < e1) {
        int s = __ldg(&esrc[e]);
        float wd = __ldg(&dinv[s]);
        while (true) {
            uint2 u = ((const uint2*)(m + (size_t)s * HDIM))[j];
            int sn = 0; float wdn = 0.f;
            if (e + 1 < e1) { sn = __ldg(&esrc[e + 1]); wdn = __ldg(&dinv[sn]); }
            float w = wd * di;
            float2 f0 = __half22float2(*(__half2*)&u.x);
            float2 f1 = __half22float2(*(__half2*)&u.y);
            a.x = fmaf(w, f0.x, a.x); a.y = fmaf(w, f0.y, a.y);
            a.z = fmaf(w, f1.x, a.z); a.w = fmaf(w, f1.y, a.w);
            e++;
            if (e >= e1) break;
            s = sn; wd = wdn;
        }
    }

    a.x = fmaxf(a.x, 0.f); a.y = fmaxf(a.y, 0.f);
    a.z = fmaxf(a.z, 0.f); a.w = fmaxf(a.w, 0.f);

    if (outf) {
        ((float4*)(outf + (size_t)node * HDIM))[j] = a;
    } else {
        uint32_t h01, h23, l01, l23;
        asm("cvt.rn.bf16x2.f32 %0, %1, %2;" : "=r"(h01) : "f"(a.y), "f"(a.x));
        asm("cvt.rn.bf16x2.f32 %0, %1, %2;" : "=r"(h23) : "f"(a.w), "f"(a.z));
        float r0 = a.x - __uint_as_float(h01 << 16);
        float r1 = a.y - __uint_as_float(h01 & 0xFFFF0000u);
        float r2 = a.z - __uint_as_float(h23 << 16);
        float r3 = a.w - __uint_as_float(h23 & 0xFFFF0000u);
        asm("cvt.rn.bf16x2.f32 %0, %1, %2;" : "=r"(l01) : "f"(r1), "f"(r0));
        asm("cvt.rn.bf16x2.f32 %0, %1, %2;" : "=r"(l23) : "f"(r3), "f"(r2));
        ((uint2*)(outh + (size_t)node * HDIM))[j] = make_uint2(h01, h23);
        ((uint2*)(outl + (size_t)node * HDIM))[j] = make_uint2(l01, l23);
    }
}

extern "C" void kernel_launch(void* const* d_in, const int* in_sizes, int n_in,
                              void* d_out, int out_size)
{
    const float* x  = (const float*)d_in[0];
    const int*   ei = (const int*)d_in[1];
    const float* w1 = (const float*)d_in[2];
    const float* b1 = (const float*)d_in[3];
    const float* w2 = (const float*)d_in[4];
    const float* b2 = (const float*)d_in[5];
    const float* gw = (const float*)d_in[6];
    const float* gb = (const float*)d_in[7];

    int N = in_sizes[0] / FIN;
    int E = in_sizes[1] / 2;
    int L = in_sizes[6] / (HDIM * HDIM);
    const int* srcp = ei;
    const int* dstp = ei + E;

    float *dinv;
    int *deg, *off, *cur, *esrc, *bsum, *bpre;
    __nv_bfloat16 *wh, *wl, *xh, *xl, *th, *tl, *hh, *hl;
    __half *mf;
    cudaGetSymbolAddress((void**)&dinv, g_dinv);
    cudaGetSymbolAddress((void**)&deg,  g_deg);
    cudaGetSymbolAddress((void**)&off,  g_off);
    cudaGetSymbolAddress((void**)&cur,  g_cur);
    cudaGetSymbolAddress((void**)&esrc, g_esrc);
    cudaGetSymbolAddress((void**)&bsum, g_bsum);
    cudaGetSymbolAddress((void**)&bpre, g_bpre);
    cudaGetSymbolAddress((void**)&wh,   g_wh);
    cudaGetSymbolAddress((void**)&wl,   g_wl);
    cudaGetSymbolAddress((void**)&xh,   g_xh);
    cudaGetSymbolAddress((void**)&xl,   g_xl);
    cudaGetSymbolAddress((void**)&th,   g_th);
    cudaGetSymbolAddress((void**)&tl,   g_tl);
    cudaGetSymbolAddress((void**)&hh,   g_hh);
    cudaGetSymbolAddress((void**)&hl,   g_hl);
    cudaGetSymbolAddress((void**)&mf,   g_mf);

    cudaFuncSetAttribute(wgemm_kernel, cudaFuncAttributeMaxDynamicSharedMemorySize, WSMEM);

    int nb = (N + 255) / 256;
    int eb = (E + 255) / 256;
    const size_t WS = 256 * 256;
    dim3 gemm_grid((N + 127) / 128, 2);

    // prep passes
    wprep_kernel<<<(N * FIN + 255) / 256, 256>>>(x, xh, xl, N * FIN);
    wprep_kernel<<<(FIN * 256 + 255) / 256, 256>>>(w1, wh, wl, FIN * 256);
    wprep2_kernel<<<((1 + L) * (int)WS + 255) / 256, 256>>>(w2, gw, wh + WS, wl + WS,
                                                            (int)WS, (1 + L) * (int)WS);

    // enc1 — profiled slot #4
    wgemm_kernel<<<gemm_grid, 256, WSMEM>>>(xh, xl, wh, wl, b1,
                                            nullptr, th, tl, N, FIN, 1);
    // enc2
    wgemm_kernel<<<gemm_grid, 256, WSMEM>>>(th, tl, wh + WS, wl + WS, b2,
                                            nullptr, hh, hl, N, HDIM, 0);

    // degree/CSR build
    init_deg_kernel<<<nb, 256>>>(deg, N);
    count_deg_kernel<<<eb, 256>>>(dstp, deg, E);
    dinv_kernel<<<nb, 256>>>(deg, dinv, N);
    bsum_kernel<<<nb, 256>>>(deg, bsum, N);
    bscan_kernel<<<1, 512>>>(bsum, bpre, nb, off, N);
    off_kernel<<<nb, 256>>>(deg, bpre, off, cur, N);
    fill_kernel<<<eb, 256>>>(srcp, dstp, cur, esrc, E);

    int agg_blocks = (int)(((long long)N * 64 + 255) / 256);

    for (int l = 0; l < L; l++) {
        wgemm_kernel<<<gemm_grid, 256, WSMEM>>>(hh, hl, wh + WS * (2 + l), wl + WS * (2 + l),
                                                nullptr, mf, nullptr, nullptr, N, HDIM, 0);
        if (l == L - 1)
            aggregate_kernel<<<agg_blocks, 256>>>(mf, off, esrc, dinv, gb + (size_t)l * HDIM,
                                                  (float*)d_out, nullptr, nullptr, N);
        else
            aggregate_kernel<<<agg_blocks, 256>>>(mf, off, esrc, dinv, gb + (size_t)l * HDIM,
                                                  nullptr, hh, hl, N);
    }
}

// round 14
// speedup vs baseline: 1.1763x; 1.0089x over previous
#include <cuda_runtime.h>
#include <cuda_bf16.h>
#include <cuda_fp16.h>
#include <mma.h>
#include <cstdint>

using namespace nvcuda;

#define NODES_MAX 100000
#define EDGES_MAX 300000
#define HDIM 256
#define FIN 128

// ---------------- scratch (allocation-free rule: __device__ globals) ----------------
__device__ float g_dinv[NODES_MAX];
__device__ int   g_deg[NODES_MAX];
__device__ int   g_off[NODES_MAX + 1];
__device__ int   g_cur[NODES_MAX];
__device__ int   g_esrc[EDGES_MAX];
__device__ int   g_bsum[512];
__device__ int   g_bpre[512];
__device__ __align__(16) __nv_bfloat16 g_wh[5 * 256 * 256];
__device__ __align__(16) __nv_bfloat16 g_wl[5 * 256 * 256];
__device__ __align__(16) __nv_bfloat16 g_xh[(size_t)NODES_MAX * FIN];
__device__ __align__(16) __nv_bfloat16 g_xl[(size_t)NODES_MAX * FIN];
__device__ __align__(16) __nv_bfloat16 g_th[(size_t)NODES_MAX * HDIM];
__device__ __align__(16) __nv_bfloat16 g_tl[(size_t)NODES_MAX * HDIM];
__device__ __align__(16) __nv_bfloat16 g_hh[(size_t)NODES_MAX * HDIM];
__device__ __align__(16) __nv_bfloat16 g_hl[(size_t)NODES_MAX * HDIM];
__device__ __align__(16) __half g_mf[(size_t)NODES_MAX * HDIM];

// ---------------- degree / norm / CSR build ----------------
__global__ void init_deg_kernel(int* deg, int n) {
    int i = blockIdx.x * blockDim.x + threadIdx.x;
    if (i < n) deg[i] = 1;
}
__global__ void count_deg_kernel(const int* __restrict__ dst, int* deg, int E) {
    int i = blockIdx.x * blockDim.x + threadIdx.x;
    if (i < E) atomicAdd(&deg[dst[i]], 1);
}
__global__ void dinv_kernel(const int* __restrict__ deg, float* dinv, int n) {
    int i = blockIdx.x * blockDim.x + threadIdx.x;
    if (i < n) dinv[i] = rsqrtf((float)deg[i]);
}
__global__ void bsum_kernel(const int* __restrict__ deg, int* bsum, int n) {
    __shared__ int sh[256];
    int i = blockIdx.x * 256 + threadIdx.x;
    sh[threadIdx.x] = (i < n) ? deg[i] - 1 : 0;
    __syncthreads();
    for (int o = 128; o > 0; o >>= 1) {
        if (threadIdx.x < o) sh[threadIdx.x] += sh[threadIdx.x + o];
        __syncthreads();
    }
    if (threadIdx.x == 0) bsum[blockIdx.x] = sh[0];
}
__global__ void bscan_kernel(const int* __restrict__ bsum, int* bpre, int nb, int* off, int n) {
    __shared__ int sh[512];
    int t = threadIdx.x;
    int v = (t < nb) ? bsum[t] : 0;
    sh[t] = v; __syncthreads();
    for (int o = 1; o < 512; o <<= 1) {
        int u = (t >= o) ? sh[t - o] : 0;
        __syncthreads();
        sh[t] += u;
        __syncthreads();
    }
    if (t < nb) bpre[t] = sh[t] - v;
    if (t == 511) off[n] = sh[511];
}
__global__ void off_kernel(const int* __restrict__ deg, const int* __restrict__ bpre,
                           int* __restrict__ off, int* __restrict__ cur, int n) {
    __shared__ int sh[256];
    int i = blockIdx.x * 256 + threadIdx.x;
    int v = (i < n) ? deg[i] - 1 : 0;
    sh[threadIdx.x] = v; __syncthreads();
    for (int o = 1; o < 256; o <<= 1) {
        int u = (threadIdx.x >= o) ? sh[threadIdx.x - o] : 0;
        __syncthreads();
        sh[threadIdx.x] += u;
        __syncthreads();
    }
    if (i < n) {
        int val = bpre[blockIdx.x] + sh[threadIdx.x] - v;
        off[i] = val;
        cur[i] = val;
    }
}
__global__ void fill_kernel(const int* __restrict__ src, const int* __restrict__ dst,
                            int* cur, int* __restrict__ esrc, int E) {
    int i = blockIdx.x * blockDim.x + threadIdx.x;
    if (i < E) {
        int d = dst[i];
        int p = atomicAdd(&cur[d], 1);
        esrc[p] = src[i];
    }
}

// ---------------- fp32 -> split hi/lo bf16 ----------------
__global__ void wprep_kernel(const float* __restrict__ W, __nv_bfloat16* __restrict__ Wh,
                             __nv_bfloat16* __restrict__ Wl, int total) {
    int idx = blockIdx.x * 256 + threadIdx.x;
    if (idx >= total) return;
    float f = W[idx];
    __nv_bfloat16 hb = __float2bfloat16_rn(f);
    Wh[idx] = hb;
    Wl[idx] = __float2bfloat16_rn(f - __bfloat162float(hb));
}
__global__ void wprep2_kernel(const float* __restrict__ w2, const float* __restrict__ gw,
                              __nv_bfloat16* __restrict__ Wh, __nv_bfloat16* __restrict__ Wl,
                              int per, int total) {
    int idx = blockIdx.x * 256 + threadIdx.x;
    if (idx >= total) return;
    float f = (idx < per) ? w2[idx] : gw[idx - per];
    __nv_bfloat16 hb = __float2bfloat16_rn(f);
    Wh[idx] = hb;
    Wl[idx] = __float2bfloat16_rn(f - __bfloat162float(hb));
}

// ---------------- 3-stage async double-buffered split-bf16 wmma GEMM ----------------
#define PADA 40
#define PADB 136
#define A_ELE (128 * PADA)
#define B_ELE (32 * PADB)
#define STAGE_ELE (2 * A_ELE + 2 * B_ELE)   // 18944 elems = 37888 B
#define NSTAGE 3
#define WSMEM (NSTAGE * STAGE_ELE * 2)       // 113664 B; 2 CTAs = 227328 <= 228KB

__device__ __forceinline__ void cp16p(void* sdst, const void* g, int srcsz) {
    uint32_t sa = (uint32_t)__cvta_generic_to_shared(sdst);
    asm volatile("cp.async.cg.shared.global [%0], [%1], 16, %2;"
                 :: "r"(sa), "l"(g), "r"(srcsz));
}

__global__ __launch_bounds__(256, 2)   // cap 128 regs -> 2 CTAs/SM
void wgemm_kernel(const __nv_bfloat16* __restrict__ Ah, const __nv_bfloat16* __restrict__ Al,
                  const __nv_bfloat16* __restrict__ Bh, const __nv_bfloat16* __restrict__ Bl,
                  const float* __restrict__ bias,
                  __half* __restrict__ Cf, __nv_bfloat16* __restrict__ Ch,
                  __nv_bfloat16* __restrict__ Cl,
                  int M, int K, int relu)
{
    extern __shared__ char smem[];
    __nv_bfloat16* sbase = (__nv_bfloat16*)smem;
    float* stage = (float*)smem;
    int tid = threadIdx.x;
    int wid = tid >> 5, wm = wid >> 2, wn = wid & 3;
    int row0 = blockIdx.x * 128, col0 = blockIdx.y * 128;

    wmma::fragment<wmma::accumulator, 16, 16, 16, float> acc[4][2];
    #pragma unroll
    for (int i = 0; i < 4; i++)
        #pragma unroll
        for (int j = 0; j < 2; j++) wmma::fill_fragment(acc[i][j], 0.0f);

    int NC = K >> 5;

    #define ISSUE(kc, s) do { \
        __nv_bfloat16* st = sbase + (s) * STAGE_ELE; \
        _Pragma("unroll") \
        for (int it = 0; it < 2; it++) { \
            int idx = it * 256 + tid; \
            int ar = idx >> 2, aseg = (idx & 3) * 8; \
            int grow = row0 + ar; \
            int ps = (grow < M) ? 16 : 0; \
            size_t ga = (size_t)(ps ? grow : 0) * K + (kc) * 32 + aseg; \
            cp16p(st + ar * PADA + aseg, Ah + ga, ps); \
            cp16p(st + A_ELE + ar * PADA + aseg, Al + ga, ps); \
            int br = idx >> 4, bseg = (idx & 15) * 8; \
            size_t gb = (size_t)((kc) * 32 + br) * 256 + col0 + bseg; \
            cp16p(st + 2 * A_ELE + br * PADB + bseg, Bh + gb, 16); \
            cp16p(st + 2 * A_ELE + B_ELE + br * PADB + bseg, Bl + gb, 16); \
        } \
        asm volatile("cp.async.commit_group;"); } while (0)

    ISSUE(0, 0);
    ISSUE(1, 1);

    for (int kc = 0; kc < NC; kc++) {
        int s = kc % NSTAGE;
        if (kc + 1 < NC) {
            asm volatile("cp.async.wait_group 1;" ::: "memory");
        } else {
            asm volatile("cp.async.wait_group 0;" ::: "memory");
        }
        __syncthreads();   // single barrier per chunk

        if (kc + 2 < NC) ISSUE(kc + 2, (kc + 2) % NSTAGE);

        __nv_bfloat16* sAh = sbase + s * STAGE_ELE;
        __nv_bfloat16* sAl = sAh + A_ELE;
        __nv_bfloat16* sBh = sAh + 2 * A_ELE;
        __nv_bfloat16* sBl = sBh + B_ELE;

        #pragma unroll
        for (int ks = 0; ks < 2; ks++) {
            wmma::fragment<wmma::matrix_b, 16, 16, 16, __nv_bfloat16, wmma::row_major> bh[2], bl[2];
            #pragma unroll
            for (int j = 0; j < 2; j++) {
                wmma::load_matrix_sync(bh[j], sBh + (ks * 16) * PADB + wn * 32 + j * 16, PADB);
                wmma::load_matrix_sync(bl[j], sBl + (ks * 16) * PADB + wn * 32 + j * 16, PADB);
            }
            #pragma unroll
            for (int i = 0; i < 4; i++) {
                wmma::fragment<wmma::matrix_a, 16, 16, 16, __nv_bfloat16, wmma::row_major> ah, al;
                wmma::load_matrix_sync(ah, sAh + (wm * 64 + i * 16) * PADA + ks * 16, PADA);
                wmma::load_matrix_sync(al, sAl + (wm * 64 + i * 16) * PADA + ks * 16, PADA);
                #pragma unroll
                for (int j = 0; j < 2; j++) {
                    wmma::mma_sync(acc[i][j], ah, bh[j], acc[i][j]);
                    wmma::mma_sync(acc[i][j], ah, bl[j], acc[i][j]);
                    wmma::mma_sync(acc[i][j], al, bh[j], acc[i][j]);
                }
            }
        }
    }
    #undef ISSUE

    __syncthreads();   // all MMAs done before smem reuse as epilogue stage

    #pragma unroll
    for (int i = 0; i < 4; i++)
        #pragma unroll
        for (int j = 0; j < 2; j++)
            wmma::store_matrix_sync(stage + (wm * 64 + i * 16) * 128 + wn * 32 + j * 16,
                                    acc[i][j], 128, wmma::mem_row_major);
    __syncthreads();

    #pragma unroll
    for (int it = 0; it < 16; it++) {
        int idx = it * 256 + tid;
        int r = idx >> 5;
        int c4 = (idx & 31) * 4;
        int grow = row0 + r;
        if (grow < M) {
            float4 v = *(float4*)(stage + r * 128 + c4);
            if (bias) {
                v.x += __ldg(bias + col0 + c4 + 0); v.y += __ldg(bias + col0 + c4 + 1);
                v.z += __ldg(bias + col0 + c4 + 2); v.w += __ldg(bias + col0 + c4 + 3);
            }
            if (relu) {
                v.x = fmaxf(v.x, 0.f); v.y = fmaxf(v.y, 0.f);
                v.z = fmaxf(v.z, 0.f); v.w = fmaxf(v.w, 0.f);
            }
            size_t o = (size_t)grow * 256 + col0 + c4;
            if (Cf) {
                __half2 ha = __floats2half2_rn(v.x, v.y);
                __half2 hb = __floats2half2_rn(v.z, v.w);
                uint2 pk;
                pk.x = *(uint32_t*)&ha; pk.y = *(uint32_t*)&hb;
                *(uint2*)(Cf + o) = pk;
            } else {
                uint32_t h01, h23, l01, l23;
                asm("cvt.rn.bf16x2.f32 %0, %1, %2;" : "=r"(h01) : "f"(v.y), "f"(v.x));
                asm("cvt.rn.bf16x2.f32 %0, %1, %2;" : "=r"(h23) : "f"(v.w), "f"(v.z));
                float r0 = v.x - __uint_as_float(h01 << 16);
                float r1 = v.y - __uint_as_float(h01 & 0xFFFF0000u);
                float r2 = v.z - __uint_as_float(h23 << 16);
                float r3 = v.w - __uint_as_float(h23 & 0xFFFF0000u);
                asm("cvt.rn.bf16x2.f32 %0, %1, %2;" : "=r"(l01) : "f"(r1), "f"(r0));
                asm("cvt.rn.bf16x2.f32 %0, %1, %2;" : "=r"(l23) : "f"(r3), "f"(r2));
                *(uint2*)(Ch + o) = make_uint2(h01, h23);
                *(uint2*)(Cl + o) = make_uint2(l01, l23);
            }
        }
    }
}

// ---------------- fused aggregate: 2 warps per node, fp16 gather ----------------
__global__ __launch_bounds__(256)
void aggregate_kernel(const __half* __restrict__ m, const int* __restrict__ off,
                      const int* __restrict__ esrc, const float* __restrict__ dinv,
                      const float* __restrict__ bias, float* __restrict__ outf,
                      __nv_bfloat16* __restrict__ outh, __nv_bfloat16* __restrict__ outl, int n)
{
    int gw = (blockIdx.x * blockDim.x + threadIdx.x) >> 5;
    int node = gw >> 1;
    int half_ = gw & 1;
    int lane = threadIdx.x & 31;
    if (node >= n) return;
    int j = half_ * 32 + lane;

    float di = __ldg(&dinv[node]);
    float4 a = ((const float4*)bias)[j];

    float ws = di * di;
    {
        uint2 u = ((const uint2*)(m + (size_t)node * HDIM))[j];
        float2 f0 = __half22float2(*(__half2*)&u.x);
        float2 f1 = __half22float2(*(__half2*)&u.y);
        a.x = fmaf(ws, f0.x, a.x); a.y = fmaf(ws, f0.y, a.y);
        a.z = fmaf(ws, f1.x, a.z); a.w = fmaf(ws, f1.y, a.w);
    }

    int e = __ldg(&off[node]);
    int e1 = __ldg(&off[node + 1]);

    if (e < e1) {
        int s = __ldg(&esrc[e]);
        float wd = __ldg(&dinv[s]);
        while (true) {
            uint2 u = ((const uint2*)(m + (size_t)s * HDIM))[j];
            int sn = 0; float wdn = 0.f;
            if (e + 1 < e1) { sn = __ldg(&esrc[e + 1]); wdn = __ldg(&dinv[sn]); }
            float w = wd * di;
            float2 f0 = __half22float2(*(__half2*)&u.x);
            float2 f1 = __half22float2(*(__half2*)&u.y);
            a.x = fmaf(w, f0.x, a.x); a.y = fmaf(w, f0.y, a.y);
            a.z = fmaf(w, f1.x, a.z); a.w = fmaf(w, f1.y, a.w);
            e++;
            if (e >= e1) break;
            s = sn; wd = wdn;
        }
    }

    a.x = fmaxf(a.x, 0.f); a.y = fmaxf(a.y, 0.f);
    a.z = fmaxf(a.z, 0.f); a.w = fmaxf(a.w, 0.f);

    if (outf) {
        ((float4*)(outf + (size_t)node * HDIM))[j] = a;
    } else {
        uint32_t h01, h23, l01, l23;
        asm("cvt.rn.bf16x2.f32 %0, %1, %2;" : "=r"(h01) : "f"(a.y), "f"(a.x));
        asm("cvt.rn.bf16x2.f32 %0, %1, %2;" : "=r"(h23) : "f"(a.w), "f"(a.z));
        float r0 = a.x - __uint_as_float(h01 << 16);
        float r1 = a.y - __uint_as_float(h01 & 0xFFFF0000u);
        float r2 = a.z - __uint_as_float(h23 << 16);
        float r3 = a.w - __uint_as_float(h23 & 0xFFFF0000u);
        asm("cvt.rn.bf16x2.f32 %0, %1, %2;" : "=r"(l01) : "f"(r1), "f"(r0));
        asm("cvt.rn.bf16x2.f32 %0, %1, %2;" : "=r"(l23) : "f"(r3), "f"(r2));
        ((uint2*)(outh + (size_t)node * HDIM))[j] = make_uint2(h01, h23);
        ((uint2*)(outl + (size_t)node * HDIM))[j] = make_uint2(l01, l23);
    }
}

extern "C" void kernel_launch(void* const* d_in, const int* in_sizes, int n_in,
                              void* d_out, int out_size)
{
    const float* x  = (const float*)d_in[0];
    const int*   ei = (const int*)d_in[1];
    const float* w1 = (const float*)d_in[2];
    const float* b1 = (const float*)d_in[3];
    const float* w2 = (const float*)d_in[4];
    const float* b2 = (const float*)d_in[5];
    const float* gw = (const float*)d_in[6];
    const float* gb = (const float*)d_in[7];

    int N = in_sizes[0] / FIN;
    int E = in_sizes[1] / 2;
    int L = in_sizes[6] / (HDIM * HDIM);
    const int* srcp = ei;
    const int* dstp = ei + E;

    float *dinv;
    int *deg, *off, *cur, *esrc, *bsum, *bpre;
    __nv_bfloat16 *wh, *wl, *xh, *xl, *th, *tl, *hh, *hl;
    __half *mf;
    cudaGetSymbolAddress((void**)&dinv, g_dinv);
    cudaGetSymbolAddress((void**)&deg,  g_deg);
    cudaGetSymbolAddress((void**)&off,  g_off);
    cudaGetSymbolAddress((void**)&cur,  g_cur);
    cudaGetSymbolAddress((void**)&esrc, g_esrc);
    cudaGetSymbolAddress((void**)&bsum, g_bsum);
    cudaGetSymbolAddress((void**)&bpre, g_bpre);
    cudaGetSymbolAddress((void**)&wh,   g_wh);
    cudaGetSymbolAddress((void**)&wl,   g_wl);
    cudaGetSymbolAddress((void**)&xh,   g_xh);
    cudaGetSymbolAddress((void**)&xl,   g_xl);
    cudaGetSymbolAddress((void**)&th,   g_th);
    cudaGetSymbolAddress((void**)&tl,   g_tl);
    cudaGetSymbolAddress((void**)&hh,   g_hh);
    cudaGetSymbolAddress((void**)&hl,   g_hl);
    cudaGetSymbolAddress((void**)&mf,   g_mf);

    cudaFuncSetAttribute(wgemm_kernel, cudaFuncAttributeMaxDynamicSharedMemorySize, WSMEM);

    int nb = (N + 255) / 256;
    int eb = (E + 255) / 256;
    const size_t WS = 256 * 256;
    dim3 gemm_grid((N + 127) / 128, 2);

    // prep passes
    wprep_kernel<<<(N * FIN + 255) / 256, 256>>>(x, xh, xl, N * FIN);
    wprep_kernel<<<(FIN * 256 + 255) / 256, 256>>>(w1, wh, wl, FIN * 256);
    wprep2_kernel<<<((1 + L) * (int)WS + 255) / 256, 256>>>(w2, gw, wh + WS, wl + WS,
                                                            (int)WS, (1 + L) * (int)WS);

    // enc1 — profiled slot #4
    wgemm_kernel<<<gemm_grid, 256, WSMEM>>>(xh, xl, wh, wl, b1,
                                            nullptr, th, tl, N, FIN, 1);
    // enc2
    wgemm_kernel<<<gemm_grid, 256, WSMEM>>>(th, tl, wh + WS, wl + WS, b2,
                                            nullptr, hh, hl, N, HDIM, 0);

    // degree/CSR build
    init_deg_kernel<<<nb, 256>>>(deg, N);
    count_deg_kernel<<<eb, 256>>>(dstp, deg, E);
    dinv_kernel<<<nb, 256>>>(deg, dinv, N);
    bsum_kernel<<<nb, 256>>>(deg, bsum, N);
    bscan_kernel<<<1, 512>>>(bsum, bpre, nb, off, N);
    off_kernel<<<nb, 256>>>(deg, bpre, off, cur, N);
    fill_kernel<<<eb, 256>>>(srcp, dstp, cur, esrc, E);

    int agg_blocks = (int)(((long long)N * 64 + 255) / 256);

    for (int l = 0; l < L; l++) {
        wgemm_kernel<<<gemm_grid, 256, WSMEM>>>(hh, hl, wh + WS * (2 + l), wl + WS * (2 + l),
                                                nullptr, mf, nullptr, nullptr, N, HDIM, 0);
        if (l == L - 1)
            aggregate_kernel<<<agg_blocks, 256>>>(mf, off, esrc, dinv, gb + (size_t)l * HDIM,
                                                  (float*)d_out, nullptr, nullptr, N);
        else
            aggregate_kernel<<<agg_blocks, 256>>>(mf, off, esrc, dinv, gb + (size_t)l * HDIM,
                                                  nullptr, hh, hl, N);
    }
}

// round 15
// speedup vs baseline: 1.6822x; 1.4301x over previous
#include <cuda_runtime.h>
#include <cuda_fp16.h>
#include <mma.h>
#include <cstdint>

using namespace nvcuda;

#define NODES_MAX 100000
#define EDGES_MAX 300000
#define HDIM 256
#define FIN 128

// ---------------- scratch (allocation-free rule: __device__ globals) ----------------
__device__ float g_dinv[NODES_MAX];
__device__ int   g_deg[NODES_MAX];
__device__ int   g_off[NODES_MAX + 1];
__device__ int   g_cur[NODES_MAX];
__device__ int   g_esrc[EDGES_MAX];
__device__ int   g_bsum[512];
__device__ int   g_bpre[512];
// split-fp16 weights [K,256], 5 slots
__device__ __align__(16) __half g_wh[5 * 256 * 256];
__device__ __align__(16) __half g_wl[5 * 256 * 256];
// fp16 activations
__device__ __align__(16) __half g_x16[(size_t)NODES_MAX * FIN];
__device__ __align__(16) __half g_t[(size_t)NODES_MAX * HDIM];
__device__ __align__(16) __half g_h[(size_t)NODES_MAX * HDIM];
__device__ __align__(16) __half g_mf[(size_t)NODES_MAX * HDIM];

// ---------------- degree / norm / CSR build ----------------
__global__ void init_deg_kernel(int* deg, int n) {
    int i = blockIdx.x * blockDim.x + threadIdx.x;
    if (i < n) deg[i] = 1;
}
__global__ void count_deg_kernel(const int* __restrict__ dst, int* deg, int E) {
    int i = blockIdx.x * blockDim.x + threadIdx.x;
    if (i < E) atomicAdd(&deg[dst[i]], 1);
}
__global__ void dinv_kernel(const int* __restrict__ deg, float* dinv, int n) {
    int i = blockIdx.x * blockDim.x + threadIdx.x;
    if (i < n) dinv[i] = rsqrtf((float)deg[i]);
}
__global__ void bsum_kernel(const int* __restrict__ deg, int* bsum, int n) {
    __shared__ int sh[256];
    int i = blockIdx.x * 256 + threadIdx.x;
    sh[threadIdx.x] = (i < n) ? deg[i] - 1 : 0;
    __syncthreads();
    for (int o = 128; o > 0; o >>= 1) {
        if (threadIdx.x < o) sh[threadIdx.x] += sh[threadIdx.x + o];
        __syncthreads();
    }
    if (threadIdx.x == 0) bsum[blockIdx.x] = sh[0];
}
__global__ void bscan_kernel(const int* __restrict__ bsum, int* bpre, int nb, int* off, int n) {
    __shared__ int sh[512];
    int t = threadIdx.x;
    int v = (t < nb) ? bsum[t] : 0;
    sh[t] = v; __syncthreads();
    for (int o = 1; o < 512; o <<= 1) {
        int u = (t >= o) ? sh[t - o] : 0;
        __syncthreads();
        sh[t] += u;
        __syncthreads();
    }
    if (t < nb) bpre[t] = sh[t] - v;
    if (t == 511) off[n] = sh[511];
}
__global__ void off_kernel(const int* __restrict__ deg, const int* __restrict__ bpre,
                           int* __restrict__ off, int* __restrict__ cur, int n) {
    __shared__ int sh[256];
    int i = blockIdx.x * 256 + threadIdx.x;
    int v = (i < n) ? deg[i] - 1 : 0;
    sh[threadIdx.x] = v; __syncthreads();
    for (int o = 1; o < 256; o <<= 1) {
        int u = (threadIdx.x >= o) ? sh[threadIdx.x - o] : 0;
        __syncthreads();
        sh[threadIdx.x] += u;
        __syncthreads();
    }
    if (i < n) {
        int val = bpre[blockIdx.x] + sh[threadIdx.x] - v;
        off[i] = val;
        cur[i] = val;
    }
}
__global__ void fill_kernel(const int* __restrict__ src, const int* __restrict__ dst,
                            int* cur, int* __restrict__ esrc, int E) {
    int i = blockIdx.x * blockDim.x + threadIdx.x;
    if (i < E) {
        int d = dst[i];
        int p = atomicAdd(&cur[d], 1);
        esrc[p] = src[i];
    }
}

// ---------------- prep: x fp32 -> fp16; W fp32 -> split hi/lo fp16 ----------------
__global__ void xprep_kernel(const float* __restrict__ X, __half* __restrict__ X16, int total) {
    int idx = blockIdx.x * 256 + threadIdx.x;
    if (idx >= total) return;
    X16[idx] = __float2half_rn(X[idx]);
}
__global__ void wprep_kernel(const float* __restrict__ W, __half* __restrict__ Wh,
                             __half* __restrict__ Wl, int total) {
    int idx = blockIdx.x * 256 + threadIdx.x;
    if (idx >= total) return;
    float f = W[idx];
    __half hb = __float2half_rn(f);
    Wh[idx] = hb;
    Wl[idx] = __float2half_rn(f - __half2float(hb));
}
__global__ void wprep2_kernel(const float* __restrict__ w2, const float* __restrict__ gw,
                              __half* __restrict__ Wh, __half* __restrict__ Wl,
                              int per, int total) {
    int idx = blockIdx.x * 256 + threadIdx.x;
    if (idx >= total) return;
    float f = (idx < per) ? w2[idx] : gw[idx - per];
    __half hb = __float2half_rn(f);
    Wh[idx] = hb;
    Wl[idx] = __float2half_rn(f - __half2float(hb));
}

// ---------------- 3-stage async fp16 x split-fp16 wmma GEMM ----------------
// C[M,256] = A[M,K](fp16) @ (Wh + Wl). Output fp16.
#define PADA 40
#define PADB 136
#define A_ELE (128 * PADA)                  // 5120 halfs
#define B_ELE (32 * PADB)                   // 4352 halfs
#define STAGE_ELE (A_ELE + 2 * B_ELE)       // 13824 halfs = 27648 B
#define NSTAGE 3
#define WSMEM (NSTAGE * STAGE_ELE * 2)      // 82944 B; 2 CTAs = 165888 <= 228KB

__device__ __forceinline__ void cp16p(void* sdst, const void* g, int srcsz) {
    uint32_t sa = (uint32_t)__cvta_generic_to_shared(sdst);
    asm volatile("cp.async.cg.shared.global [%0], [%1], 16, %2;"
                 :: "r"(sa), "l"(g), "r"(srcsz));
}

__global__ __launch_bounds__(256, 2)   // 2 CTAs/SM
void wgemm_kernel(const __half* __restrict__ A,
                  const __half* __restrict__ Bh, const __half* __restrict__ Bl,
                  const float* __restrict__ bias, __half* __restrict__ C,
                  int M, int K, int relu)
{
    extern __shared__ char smem[];
    __half* sbase = (__half*)smem;
    float* stage = (float*)smem;
    int tid = threadIdx.x;
    int wid = tid >> 5, wm = wid >> 2, wn = wid & 3;
    int row0 = blockIdx.x * 128, col0 = blockIdx.y * 128;

    wmma::fragment<wmma::accumulator, 16, 16, 16, float> acc[4][2];
    #pragma unroll
    for (int i = 0; i < 4; i++)
        #pragma unroll
        for (int j = 0; j < 2; j++) wmma::fill_fragment(acc[i][j], 0.0f);

    int NC = K >> 5;

    #define ISSUE(kc, s) do { \
        __half* st = sbase + (s) * STAGE_ELE; \
        _Pragma("unroll") \
        for (int it = 0; it < 2; it++) { \
            int idx = it * 256 + tid; \
            int ar = idx >> 2, aseg = (idx & 3) * 8; \
            int grow = row0 + ar; \
            int ps = (grow < M) ? 16 : 0; \
            size_t ga = (size_t)(ps ? grow : 0) * K + (kc) * 32 + aseg; \
            cp16p(st + ar * PADA + aseg, A + ga, ps); \
            int br = idx >> 4, bseg = (idx & 15) * 8; \
            size_t gb = (size_t)((kc) * 32 + br) * 256 + col0 + bseg; \
            cp16p(st + A_ELE + br * PADB + bseg, Bh + gb, 16); \
            cp16p(st + A_ELE + B_ELE + br * PADB + bseg, Bl + gb, 16); \
        } \
        asm volatile("cp.async.commit_group;"); } while (0)

    ISSUE(0, 0);
    ISSUE(1, 1);

    for (int kc = 0; kc < NC; kc++) {
        int s = kc % NSTAGE;
        if (kc + 1 < NC) {
            asm volatile("cp.async.wait_group 1;" ::: "memory");
        } else {
            asm volatile("cp.async.wait_group 0;" ::: "memory");
        }
        __syncthreads();

        if (kc + 2 < NC) ISSUE(kc + 2, (kc + 2) % NSTAGE);

        __half* sA  = sbase + s * STAGE_ELE;
        __half* sBh = sA + A_ELE;
        __half* sBl = sBh + B_ELE;

        #pragma unroll
        for (int ks = 0; ks < 2; ks++) {
            wmma::fragment<wmma::matrix_b, 16, 16, 16, __half, wmma::row_major> bh[2], bl[2];
            #pragma unroll
            for (int j = 0; j < 2; j++) {
                wmma::load_matrix_sync(bh[j], sBh + (ks * 16) * PADB + wn * 32 + j * 16, PADB);
                wmma::load_matrix_sync(bl[j], sBl + (ks * 16) * PADB + wn * 32 + j * 16, PADB);
            }
            #pragma unroll
            for (int i = 0; i < 4; i++) {
                wmma::fragment<wmma::matrix_a, 16, 16, 16, __half, wmma::row_major> af;
                wmma::load_matrix_sync(af, sA + (wm * 64 + i * 16) * PADA + ks * 16, PADA);
                #pragma unroll
                for (int j = 0; j < 2; j++) {
                    wmma::mma_sync(acc[i][j], af, bh[j], acc[i][j]);
                    wmma::mma_sync(acc[i][j], af, bl[j], acc[i][j]);
                }
            }
        }
    }
    #undef ISSUE

    __syncthreads();   // all MMAs done before smem reuse as epilogue stage

    #pragma unroll
    for (int i = 0; i < 4; i++)
        #pragma unroll
        for (int j = 0; j < 2; j++)
            wmma::store_matrix_sync(stage + (wm * 64 + i * 16) * 128 + wn * 32 + j * 16,
                                    acc[i][j], 128, wmma::mem_row_major);
    __syncthreads();

    #pragma unroll
    for (int it = 0; it < 16; it++) {
        int idx = it * 256 + tid;
        int r = idx >> 5;
        int c4 = (idx & 31) * 4;
        int grow = row0 + r;
        if (grow < M) {
            float4 v = *(float4*)(stage + r * 128 + c4);
            if (bias) {
                v.x += __ldg(bias + col0 + c4 + 0); v.y += __ldg(bias + col0 + c4 + 1);
                v.z += __ldg(bias + col0 + c4 + 2); v.w += __ldg(bias + col0 + c4 + 3);
            }
            if (relu) {
                v.x = fmaxf(v.x, 0.f); v.y = fmaxf(v.y, 0.f);
                v.z = fmaxf(v.z, 0.f); v.w = fmaxf(v.w, 0.f);
            }
            __half2 ha = __floats2half2_rn(v.x, v.y);
            __half2 hb = __floats2half2_rn(v.z, v.w);
            uint2 pk;
            pk.x = *(uint32_t*)&ha; pk.y = *(uint32_t*)&hb;
            *(uint2*)(C + (size_t)grow * 256 + col0 + c4) = pk;
        }
    }
}

// ---------------- fused aggregate: 2 warps per node, fp16 gather ----------------
// out = relu(bias + dinv^2*m[i] + sum dinv[s]*dinv[i]*m[s]); fp32 out (final) OR fp16 out.
__global__ __launch_bounds__(256)
void aggregate_kernel(const __half* __restrict__ m, const int* __restrict__ off,
                      const int* __restrict__ esrc, const float* __restrict__ dinv,
                      const float* __restrict__ bias, float* __restrict__ outf,
                      __half* __restrict__ outh, int n)
{
    int gw = (blockIdx.x * blockDim.x + threadIdx.x) >> 5;
    int node = gw >> 1;
    int half_ = gw & 1;
    int lane = threadIdx.x & 31;
    if (node >= n) return;
    int j = half_ * 32 + lane;   // 4-col group index 0..63

    float di = __ldg(&dinv[node]);
    float4 a = ((const float4*)bias)[j];

    float ws = di * di;
    {
        uint2 u = ((const uint2*)(m + (size_t)node * HDIM))[j];
        float2 f0 = __half22float2(*(__half2*)&u.x);
        float2 f1 = __half22float2(*(__half2*)&u.y);
        a.x = fmaf(ws, f0.x, a.x); a.y = fmaf(ws, f0.y, a.y);
        a.z = fmaf(ws, f1.x, a.z); a.w = fmaf(ws, f1.y, a.w);
    }

    int e = __ldg(&off[node]);
    int e1 = __ldg(&off[node + 1]);

    if (e < e1) {
        int s = __ldg(&esrc[e]);
        float wd = __ldg(&dinv[s]);
        while (true) {
            uint2 u = ((const uint2*)(m + (size_t)s * HDIM))[j];
            int sn = 0; float wdn = 0.f;
            if (e + 1 < e1) { sn = __ldg(&esrc[e + 1]); wdn = __ldg(&dinv[sn]); }
            float w = wd * di;
            float2 f0 = __half22float2(*(__half2*)&u.x);
            float2 f1 = __half22float2(*(__half2*)&u.y);
            a.x = fmaf(w, f0.x, a.x); a.y = fmaf(w, f0.y, a.y);
            a.z = fmaf(w, f1.x, a.z); a.w = fmaf(w, f1.y, a.w);
            e++;
            if (e >= e1) break;
            s = sn; wd = wdn;
        }
    }

    a.x = fmaxf(a.x, 0.f); a.y = fmaxf(a.y, 0.f);
    a.z = fmaxf(a.z, 0.f); a.w = fmaxf(a.w, 0.f);

    if (outf) {
        ((float4*)(outf + (size_t)node * HDIM))[j] = a;
    } else {
        __half2 ha = __floats2half2_rn(a.x, a.y);
        __half2 hb = __floats2half2_rn(a.z, a.w);
        uint2 pk;
        pk.x = *(uint32_t*)&ha; pk.y = *(uint32_t*)&hb;
        ((uint2*)(outh + (size_t)node * HDIM))[j] = pk;
    }
}

extern "C" void kernel_launch(void* const* d_in, const int* in_sizes, int n_in,
                              void* d_out, int out_size)
{
    const float* x  = (const float*)d_in[0];
    const int*   ei = (const int*)d_in[1];
    const float* w1 = (const float*)d_in[2];
    const float* b1 = (const float*)d_in[3];
    const float* w2 = (const float*)d_in[4];
    const float* b2 = (const float*)d_in[5];
    const float* gw = (const float*)d_in[6];
    const float* gb = (const float*)d_in[7];

    int N = in_sizes[0] / FIN;
    int E = in_sizes[1] / 2;
    int L = in_sizes[6] / (HDIM * HDIM);
    const int* srcp = ei;
    const int* dstp = ei + E;

    float *dinv;
    int *deg, *off, *cur, *esrc, *bsum, *bpre;
    __half *wh, *wl, *x16, *t, *h, *mf;
    cudaGetSymbolAddress((void**)&dinv, g_dinv);
    cudaGetSymbolAddress((void**)&deg,  g_deg);
    cudaGetSymbolAddress((void**)&off,  g_off);
    cudaGetSymbolAddress((void**)&cur,  g_cur);
    cudaGetSymbolAddress((void**)&esrc, g_esrc);
    cudaGetSymbolAddress((void**)&bsum, g_bsum);
    cudaGetSymbolAddress((void**)&bpre, g_bpre);
    cudaGetSymbolAddress((void**)&wh,   g_wh);
    cudaGetSymbolAddress((void**)&wl,   g_wl);
    cudaGetSymbolAddress((void**)&x16,  g_x16);
    cudaGetSymbolAddress((void**)&t,    g_t);
    cudaGetSymbolAddress((void**)&h,    g_h);
    cudaGetSymbolAddress((void**)&mf,   g_mf);

    cudaFuncSetAttribute(wgemm_kernel, cudaFuncAttributeMaxDynamicSharedMemorySize, WSMEM);

    int nb = (N + 255) / 256;
    int eb = (E + 255) / 256;
    const size_t WS = 256 * 256;
    dim3 gemm_grid((N + 127) / 128, 2);

    // prep passes (3 launches)
    xprep_kernel<<<(N * FIN + 255) / 256, 256>>>(x, x16, N * FIN);
    wprep_kernel<<<(FIN * 256 + 255) / 256, 256>>>(w1, wh, wl, FIN * 256);
    wprep2_kernel<<<((1 + L) * (int)WS + 255) / 256, 256>>>(w2, gw, wh + WS, wl + WS,
                                                            (int)WS, (1 + L) * (int)WS);

    // enc1 — profiled slot #4
    wgemm_kernel<<<gemm_grid, 256, WSMEM>>>(x16, wh, wl, b1, t, N, FIN, 1);
    // enc2
    wgemm_kernel<<<gemm_grid, 256, WSMEM>>>(t, wh + WS, wl + WS, b2, h, N, HDIM, 0);

    // degree/CSR build
    init_deg_kernel<<<nb, 256>>>(deg, N);
    count_deg_kernel<<<eb, 256>>>(dstp, deg, E);
    dinv_kernel<<<nb, 256>>>(deg, dinv, N);
    bsum_kernel<<<nb, 256>>>(deg, bsum, N);
    bscan_kernel<<<1, 512>>>(bsum, bpre, nb, off, N);
    off_kernel<<<nb, 256>>>(deg, bpre, off, cur, N);
    fill_kernel<<<eb, 256>>>(srcp, dstp, cur, esrc, E);

    int agg_blocks = (int)(((long long)N * 64 + 255) / 256);

    for (int l = 0; l < L; l++) {
        wgemm_kernel<<<gemm_grid, 256, WSMEM>>>(h, wh + WS * (2 + l), wl + WS * (2 + l),
                                                nullptr, mf, N, HDIM, 0);
        if (l == L - 1)
            aggregate_kernel<<<agg_blocks, 256>>>(mf, off, esrc, dinv, gb + (size_t)l * HDIM,
                                                  (float*)d_out, nullptr, N);
        else
            aggregate_kernel<<<agg_blocks, 256>>>(mf, off, esrc, dinv, gb + (size_t)l * HDIM,
                                                  nullptr, h, N);
    }
}